// round 6
// baseline (speedup 1.0000x reference)
#include <cuda_runtime.h>

#define IMG_H 512
#define IMG_W 512
#define TH 32
#define TW 32
#define HALO 5
#define INW (TW + 2*HALO)   // 42 vertical-result columns
#define SW  (INW + 1)       // 43, odd stride vs 32 banks (conflict-free)
#define PLANE (TH*SW)       // 1376
#define NBX (IMG_W/TW)      // 16
#define NBY (IMG_H/TH)      // 16
#define NBZ 96
#define NBLOCKS (NBX*NBY*NBZ)  // 24576
#define CHUNK 4
#define NCHUNKS (TH/CHUNK)     // 8
#define VITEMS (INW*NCHUNKS)   // 336 vertical work items

typedef unsigned long long ull;

__device__ float  g_partials[NBLOCKS];
__device__ double g_p2[32];

// ---- packed f32x2 helpers (sm_103a FFMA2 path) ----
__device__ __forceinline__ ull pk2(float lo, float hi) {
    ull r; asm("mov.b64 %0, {%1,%2};" : "=l"(r) : "f"(lo), "f"(hi)); return r;
}
__device__ __forceinline__ void upk2(ull v, float& lo, float& hi) {
    asm("mov.b64 {%0,%1}, %2;" : "=f"(lo), "=f"(hi) : "l"(v));
}
__device__ __forceinline__ ull fma2(ull a, ull b, ull c) {
    ull r; asm("fma.rn.f32x2 %0, %1, %2, %3;" : "=l"(r) : "l"(a), "l"(b), "l"(c)); return r;
}
__device__ __forceinline__ ull mul2(ull a, ull b) {
    ull r; asm("mul.rn.f32x2 %0, %1, %2;" : "=l"(r) : "l"(a), "l"(b)); return r;
}

__device__ __forceinline__ float ssim_val(float mu1, float mu2, float e11, float e22, float e12) {
    const float C1 = 1e-4f;
    const float C2 = 9e-4f;
    float mu11 = mu1 * mu1;
    float mu22 = mu2 * mu2;
    float mu12 = mu1 * mu2;
    float num = (2.0f * mu12 + C1) * (2.0f * (e12 - mu12) + C2);
    float den = (mu11 + mu22 + C1) * ((e11 - mu11) + (e22 - mu22) + C2);
    return __fdividef(num, den);
}

__global__ void ssim_nop() {}

// Weight symmetry: W11[k] == W11[10-k], W5[m] == W5[4-m]. Hold only the
// distinct packs in registers (6+3 u64 = 18 regs instead of 32).
#define W2IDX(k) ((k) < 6 ? (k) : 10 - (k))
#define U2IDX(m) ((m) < 3 ? (m) : 4 - (m))

__global__ void __launch_bounds__(256, 4)
ssim_main(const float* __restrict__ g1, const float* __restrict__ g2) {
    // Gaussian weights (sigma=1.5), computed offline in double then cast.
    constexpr float W11[11] = {
        0.00102838f, 0.00759876f, 0.03600077f, 0.10936069f, 0.21300552f,
        0.26601172f,
        0.21300552f, 0.10936069f, 0.03600077f, 0.00759876f, 0.00102838f };
    constexpr float W5[5] = {
        0.12007838f, 0.23388074f, 0.29208172f, 0.23388074f, 0.12007838f };

    extern __shared__ float vp[];      // 10 planes of TH x SW (v5: 0..4, v11: 5..9)

    const int t = threadIdx.x;
    const int r0 = blockIdx.y * TH;
    const int c0 = blockIdx.x * TW;
    const float* i1 = g1 + (size_t)blockIdx.z * (IMG_H * IMG_W);
    const float* i2 = g2 + (size_t)blockIdx.z * (IMG_H * IMG_W);

    ull W2d[6], U2d[3];
    #pragma unroll
    for (int i = 0; i < 6; i++) W2d[i] = pk2(W11[i], W11[i]);
    #pragma unroll
    for (int i = 0; i < 3; i++) U2d[i] = pk2(W5[i], W5[i]);

    // ---- vertical pass: global -> regs (14-row span) -> scatter -> vp ----
    for (int i = t; i < VITEMS; i += 256) {
        int chunk = i / INW;          // 0..7
        int vcol  = i - chunk * INW;  // 0..41
        int gc = c0 - HALO + vcol;
        int grb = r0 + CHUNK * chunk - HALO;
        bool colok = (unsigned)gc < IMG_W;

        ull P11[CHUNK], S11[CHUNK], P5[CHUNK], S5[CHUNK];
        float X11[CHUNK], X5[CHUNK];
        #pragma unroll
        for (int o = 0; o < CHUNK; o++) {
            P11[o] = S11[o] = P5[o] = S5[o] = 0ULL;
            X11[o] = X5[o] = 0.f;
        }
        #pragma unroll
        for (int j = 0; j < CHUNK + 10; j++) {   // 14 input rows
            int gr = grb + j;
            float x = 0.f, y = 0.f;
            if (colok && (unsigned)gr < IMG_H) {
                int gi = gr * IMG_W + gc;
                x = i1[gi];
                y = i2[gi];
            }
            ull p  = pk2(x, y);
            ull sq = mul2(p, p);
            float xy = x * y;
            #pragma unroll
            for (int o = 0; o < CHUNK; o++) {
                int k = j - o;                 // tap index for output row o
                if (k >= 0 && k < 11) {
                    P11[o] = fma2(W2d[W2IDX(k)], p,  P11[o]);
                    S11[o] = fma2(W2d[W2IDX(k)], sq, S11[o]);
                    X11[o] = fmaf(W11[k], xy, X11[o]);
                }
                if (k >= 3 && k < 8) {
                    P5[o] = fma2(U2d[U2IDX(k-3)], p,  P5[o]);
                    S5[o] = fma2(U2d[U2IDX(k-3)], sq, S5[o]);
                    X5[o] = fmaf(W5[k-3], xy, X5[o]);
                }
            }
        }
        #pragma unroll
        for (int o = 0; o < CHUNK; o++) {
            int off = (CHUNK * chunk + o) * SW + vcol;
            float lo, hi;
            upk2(P5[o], lo, hi);  vp[0*PLANE + off] = lo; vp[1*PLANE + off] = hi;
            upk2(S5[o], lo, hi);  vp[2*PLANE + off] = lo; vp[3*PLANE + off] = hi;
            vp[4*PLANE + off] = X5[o];
            upk2(P11[o], lo, hi); vp[5*PLANE + off] = lo; vp[6*PLANE + off] = hi;
            upk2(S11[o], lo, hi); vp[7*PLANE + off] = lo; vp[8*PLANE + off] = hi;
            vp[9*PLANE + off] = X11[o];
        }
    }
    __syncthreads();

    // ---- horizontal pass (4 consecutive output columns per thread) ----
    const int rr = t >> 3;          // 0..31
    const int cc = (t & 7) * 4;     // 0,4,...,28
    const float* b5  = vp + rr * SW + cc;
    const float* b11 = b5 + 5 * PLANE;

    float lsum = 0.f;

    // map (kh=5, kw=11): h11 over v5 planes
    {
        ull aP[4], aS[4];
        float aC[4];
        #pragma unroll
        for (int p = 0; p < 4; p++) { aP[p] = 0ULL; aS[p] = 0ULL; aC[p] = 0.f; }
        #pragma unroll
        for (int dx = 0; dx < 14; dx++) {
            float v0 = b5[dx];
            float v1 = b5[PLANE + dx];
            float v2 = b5[2*PLANE + dx];
            float v3 = b5[3*PLANE + dx];
            float v4 = b5[4*PLANE + dx];
            ull pP = pk2(v0, v1);
            ull pS = pk2(v2, v3);
            #pragma unroll
            for (int p = 0; p < 4; p++) {
                int k = dx - p;
                if (k >= 0 && k < 11) {
                    aP[p] = fma2(W2d[W2IDX(k)], pP, aP[p]);
                    aS[p] = fma2(W2d[W2IDX(k)], pS, aS[p]);
                    aC[p] = fmaf(W11[k], v4, aC[p]);
                }
            }
        }
        #pragma unroll
        for (int p = 0; p < 4; p++) {
            float m1, m2, e11, e22;
            upk2(aP[p], m1, m2); upk2(aS[p], e11, e22);
            lsum += ssim_val(m1, m2, e11, e22, aC[p]);
        }
    }

    // maps (11,5) via h5 and (11,11) via h11, both over v11 planes
    {
        ull bP[4], bS[4], cP[4], cS[4];
        float bC[4], cC[4];
        #pragma unroll
        for (int p = 0; p < 4; p++) {
            bP[p] = bS[p] = cP[p] = cS[p] = 0ULL;
            bC[p] = cC[p] = 0.f;
        }
        #pragma unroll
        for (int dx = 0; dx < 14; dx++) {
            float v0 = b11[dx];
            float v1 = b11[PLANE + dx];
            float v2 = b11[2*PLANE + dx];
            float v3 = b11[3*PLANE + dx];
            float v4 = b11[4*PLANE + dx];
            ull pP = pk2(v0, v1);
            ull pS = pk2(v2, v3);
            #pragma unroll
            for (int p = 0; p < 4; p++) {
                int k = dx - p;
                if (k >= 0 && k < 11) {
                    cP[p] = fma2(W2d[W2IDX(k)], pP, cP[p]);
                    cS[p] = fma2(W2d[W2IDX(k)], pS, cS[p]);
                    cC[p] = fmaf(W11[k], v4, cC[p]);
                }
                int m = k - 3;
                if (m >= 0 && m < 5) {
                    bP[p] = fma2(U2d[U2IDX(m)], pP, bP[p]);
                    bS[p] = fma2(U2d[U2IDX(m)], pS, bS[p]);
                    bC[p] = fmaf(W5[m], v4, bC[p]);
                }
            }
        }
        #pragma unroll
        for (int p = 0; p < 4; p++) {
            float m1, m2, e11, e22;
            upk2(bP[p], m1, m2); upk2(bS[p], e11, e22);
            lsum += ssim_val(m1, m2, e11, e22, bC[p]);
            upk2(cP[p], m1, m2); upk2(cS[p], e11, e22);
            lsum += ssim_val(m1, m2, e11, e22, cC[p]);
        }
    }

    // ---- block reduction -> per-block partial ----
    #pragma unroll
    for (int o = 16; o; o >>= 1) lsum += __shfl_xor_sync(0xffffffffu, lsum, o);
    __shared__ float warp_sums[8];
    if ((t & 31) == 0) warp_sums[t >> 5] = lsum;
    __syncthreads();
    if (t == 0) {
        float s = 0.f;
        #pragma unroll
        for (int w = 0; w < 8; w++) s += warp_sums[w];
        g_partials[(blockIdx.z * NBY + blockIdx.y) * NBX + blockIdx.x] = s;
    }
}

// stage 1: 32 blocks x 256 threads, each block sums 768 partials
__global__ void ssim_reduce1() {
    int t = threadIdx.x;
    int base = blockIdx.x * 768;
    double s = (double)g_partials[base + t]
             + (double)g_partials[base + t + 256]
             + (double)g_partials[base + t + 512];
    #pragma unroll
    for (int o = 16; o; o >>= 1) s += __shfl_xor_sync(0xffffffffu, s, o);
    __shared__ double ws[8];
    if ((t & 31) == 0) ws[t >> 5] = s;
    __syncthreads();
    if (t == 0) {
        double v = 0.0;
        #pragma unroll
        for (int w = 0; w < 8; w++) v += ws[w];
        g_p2[blockIdx.x] = v;
    }
}

// stage 2: single warp
__global__ void ssim_reduce2(float* __restrict__ out) {
    int t = threadIdx.x;
    double v = g_p2[t];
    #pragma unroll
    for (int o = 16; o; o >>= 1) v += __shfl_xor_sync(0xffffffffu, v, o);
    if (t == 0) out[0] = (float)(v / (3.0 * 25165824.0));  // 3 maps * 32*3*512*512
}

extern "C" void kernel_launch(void* const* d_in, const int* in_sizes, int n_in,
                              void* d_out, int out_size) {
    const float* img1 = (const float*)d_in[0];
    const float* img2 = (const float*)d_in[1];
    constexpr int SMEM_BYTES = 10 * PLANE * (int)sizeof(float); // 55040
    cudaFuncSetAttribute(ssim_main, cudaFuncAttributeMaxDynamicSharedMemorySize, SMEM_BYTES);
    dim3 grid(NBX, NBY, NBZ);
    // 3 nops put ssim_main at global launch index 5 == ncu's -s 5 -c 1 slot
    // (verified R3/R4/R5: profile hit ssim_main).
    ssim_nop<<<1, 32>>>();
    ssim_nop<<<1, 32>>>();
    ssim_nop<<<1, 32>>>();
    ssim_main<<<grid, 256, SMEM_BYTES>>>(img1, img2);
    ssim_reduce1<<<32, 256>>>();
    ssim_reduce2<<<1, 32>>>((float*)d_out);
}

// round 7
// speedup vs baseline: 1.0317x; 1.0317x over previous
#include <cuda_runtime.h>

#define IMG_H 512
#define IMG_W 512
#define TH 32
#define TW 32
#define HALO 5
#define INW (TW + 2*HALO)   // 42 vertical-result columns
#define SW  (INW + 1)       // 43 (odd -> conflict-free)
#define PLANE (TH*SW)       // 1376 elements per plane
#define NBX (IMG_W/TW)      // 16
#define NBY (IMG_H/TH)      // 16
#define NBZ 96
#define NBLOCKS (NBX*NBY*NBZ)  // 24576
#define CHUNK 4
#define NCHUNKS (TH/CHUNK)     // 8
#define VITEMS (INW*NCHUNKS)   // 336 vertical work items

typedef unsigned long long ull;

__device__ float  g_partials[NBLOCKS];
__device__ double g_p2[32];

// ---- packed f32x2 helpers (sm_103a FFMA2 path) ----
__device__ __forceinline__ ull pk2(float lo, float hi) {
    ull r; asm("mov.b64 %0, {%1,%2};" : "=l"(r) : "f"(lo), "f"(hi)); return r;
}
__device__ __forceinline__ void upk2(ull v, float& lo, float& hi) {
    asm("mov.b64 {%0,%1}, %2;" : "=f"(lo), "=f"(hi) : "l"(v));
}
__device__ __forceinline__ ull fma2(ull a, ull b, ull c) {
    ull r; asm("fma.rn.f32x2 %0, %1, %2, %3;" : "=l"(r) : "l"(a), "l"(b), "l"(c)); return r;
}
__device__ __forceinline__ ull mul2(ull a, ull b) {
    ull r; asm("mul.rn.f32x2 %0, %1, %2;" : "=l"(r) : "l"(a), "l"(b)); return r;
}

__device__ __forceinline__ float ssim_val(float mu1, float mu2, float e11, float e22, float e12) {
    const float C1 = 1e-4f;
    const float C2 = 9e-4f;
    float mu11 = mu1 * mu1;
    float mu22 = mu2 * mu2;
    float mu12 = mu1 * mu2;
    float num = (2.0f * mu12 + C1) * (2.0f * (e12 - mu12) + C2);
    float den = (mu11 + mu22 + C1) * ((e11 - mu11) + (e22 - mu22) + C2);
    return __fdividef(num, den);
}

__global__ void ssim_nop() {}

// Weight symmetry: W11[k] == W11[10-k], W5[m] == W5[4-m].
#define W2IDX(k) ((k) < 6 ? (k) : 10 - (k))
#define U2IDX(m) ((m) < 3 ? (m) : 4 - (m))

__global__ void __launch_bounds__(256, 3)
ssim_main(const float* __restrict__ g1, const float* __restrict__ g2) {
    // Gaussian weights (sigma=1.5), computed offline in double then cast.
    constexpr float W11[11] = {
        0.00102838f, 0.00759876f, 0.03600077f, 0.10936069f, 0.21300552f,
        0.26601172f,
        0.21300552f, 0.10936069f, 0.03600077f, 0.00759876f, 0.00102838f };
    constexpr float W5[5] = {
        0.12007838f, 0.23388074f, 0.29208172f, 0.23388074f, 0.12007838f };

    // smem: 4 pair-planes (ull) then 2 scalar xy planes (float)
    //   pair plane f at pvp[f*PLANE + row*SW + col], f: 0=P5,1=S5,2=P11,3=S11
    //   xy planes  xv[g*PLANE + ...], g: 0=xy5, 1=xy11
    extern __shared__ ull pvp[];                       // 4*PLANE ull = 44032 B
    float* xv = (float*)(pvp + 4 * PLANE);             // 2*PLANE float = 11008 B

    const int t = threadIdx.x;
    const int r0 = blockIdx.y * TH;
    const int c0 = blockIdx.x * TW;
    const float* i1 = g1 + (size_t)blockIdx.z * (IMG_H * IMG_W);
    const float* i2 = g2 + (size_t)blockIdx.z * (IMG_H * IMG_W);

    ull W2d[6], U2d[3];
    #pragma unroll
    for (int i = 0; i < 6; i++) W2d[i] = pk2(W11[i], W11[i]);
    #pragma unroll
    for (int i = 0; i < 3; i++) U2d[i] = pk2(W5[i], W5[i]);

    // ---- vertical pass: global -> regs (14-row span) -> scatter -> planes ----
    for (int i = t; i < VITEMS; i += 256) {
        int chunk = i / INW;          // 0..7
        int vcol  = i - chunk * INW;  // 0..41
        int gc = c0 - HALO + vcol;
        int grb = r0 + CHUNK * chunk - HALO;
        bool colok = (unsigned)gc < IMG_W;

        ull P11[CHUNK], S11[CHUNK], P5[CHUNK], S5[CHUNK];
        float X11[CHUNK], X5[CHUNK];
        #pragma unroll
        for (int o = 0; o < CHUNK; o++) {
            P11[o] = S11[o] = P5[o] = S5[o] = 0ULL;
            X11[o] = X5[o] = 0.f;
        }
        #pragma unroll
        for (int j = 0; j < CHUNK + 10; j++) {   // 14 input rows
            int gr = grb + j;
            float x = 0.f, y = 0.f;
            if (colok && (unsigned)gr < IMG_H) {
                int gi = gr * IMG_W + gc;
                x = i1[gi];
                y = i2[gi];
            }
            ull p  = pk2(x, y);
            ull sq = mul2(p, p);
            float xy = x * y;
            #pragma unroll
            for (int o = 0; o < CHUNK; o++) {
                int k = j - o;                 // tap index for output row o
                if (k >= 0 && k < 11) {
                    P11[o] = fma2(W2d[W2IDX(k)], p,  P11[o]);
                    S11[o] = fma2(W2d[W2IDX(k)], sq, S11[o]);
                    X11[o] = fmaf(W11[k], xy, X11[o]);
                }
                if (k >= 3 && k < 8) {
                    P5[o] = fma2(U2d[U2IDX(k-3)], p,  P5[o]);
                    S5[o] = fma2(U2d[U2IDX(k-3)], sq, S5[o]);
                    X5[o] = fmaf(W5[k-3], xy, X5[o]);
                }
            }
        }
        #pragma unroll
        for (int o = 0; o < CHUNK; o++) {
            int off = (CHUNK * chunk + o) * SW + vcol;
            pvp[0*PLANE + off] = P5[o];
            pvp[1*PLANE + off] = S5[o];
            pvp[2*PLANE + off] = P11[o];
            pvp[3*PLANE + off] = S11[o];
            xv[0*PLANE + off] = X5[o];
            xv[1*PLANE + off] = X11[o];
        }
    }
    __syncthreads();

    // ---- horizontal pass (4 consecutive output columns per thread) ----
    const int rr = t >> 3;          // 0..31
    const int cc = (t & 7) * 4;     // 0,4,...,28
    const ull*   q  = pvp + rr * SW + cc;
    const float* qx = xv  + rr * SW + cc;

    float lsum = 0.f;

    // map (kh=5, kw=11): h11 over v5 planes
    {
        ull aP[4], aS[4];
        float aC[4];
        #pragma unroll
        for (int p = 0; p < 4; p++) { aP[p] = 0ULL; aS[p] = 0ULL; aC[p] = 0.f; }
        #pragma unroll
        for (int dx = 0; dx < 14; dx++) {
            ull pP = q[dx];                 // (mu1_5, mu2_5)
            ull pS = q[PLANE + dx];         // (e11_5, e22_5)
            float v4 = qx[dx];              // xy_5
            #pragma unroll
            for (int p = 0; p < 4; p++) {
                int k = dx - p;
                if (k >= 0 && k < 11) {
                    aP[p] = fma2(W2d[W2IDX(k)], pP, aP[p]);
                    aS[p] = fma2(W2d[W2IDX(k)], pS, aS[p]);
                    aC[p] = fmaf(W11[k], v4, aC[p]);
                }
            }
        }
        #pragma unroll
        for (int p = 0; p < 4; p++) {
            float m1, m2, e11, e22;
            upk2(aP[p], m1, m2); upk2(aS[p], e11, e22);
            lsum += ssim_val(m1, m2, e11, e22, aC[p]);
        }
    }

    // maps (11,5) via h5 and (11,11) via h11, both over v11 planes
    {
        ull bP[4], bS[4], cP[4], cS[4];
        float bC[4], cC[4];
        #pragma unroll
        for (int p = 0; p < 4; p++) {
            bP[p] = bS[p] = cP[p] = cS[p] = 0ULL;
            bC[p] = cC[p] = 0.f;
        }
        #pragma unroll
        for (int dx = 0; dx < 14; dx++) {
            ull pP = q[2*PLANE + dx];       // (mu1_11, mu2_11)
            ull pS = q[3*PLANE + dx];       // (e11_11, e22_11)
            float v4 = qx[PLANE + dx];      // xy_11
            #pragma unroll
            for (int p = 0; p < 4; p++) {
                int k = dx - p;
                if (k >= 0 && k < 11) {
                    cP[p] = fma2(W2d[W2IDX(k)], pP, cP[p]);
                    cS[p] = fma2(W2d[W2IDX(k)], pS, cS[p]);
                    cC[p] = fmaf(W11[k], v4, cC[p]);
                }
                int m = k - 3;
                if (m >= 0 && m < 5) {
                    bP[p] = fma2(U2d[U2IDX(m)], pP, bP[p]);
                    bS[p] = fma2(U2d[U2IDX(m)], pS, bS[p]);
                    bC[p] = fmaf(W5[m], v4, bC[p]);
                }
            }
        }
        #pragma unroll
        for (int p = 0; p < 4; p++) {
            float m1, m2, e11, e22;
            upk2(bP[p], m1, m2); upk2(bS[p], e11, e22);
            lsum += ssim_val(m1, m2, e11, e22, bC[p]);
            upk2(cP[p], m1, m2); upk2(cS[p], e11, e22);
            lsum += ssim_val(m1, m2, e11, e22, cC[p]);
        }
    }

    // ---- block reduction -> per-block partial ----
    #pragma unroll
    for (int o = 16; o; o >>= 1) lsum += __shfl_xor_sync(0xffffffffu, lsum, o);
    __shared__ float warp_sums[8];
    if ((t & 31) == 0) warp_sums[t >> 5] = lsum;
    __syncthreads();
    if (t == 0) {
        float s = 0.f;
        #pragma unroll
        for (int w = 0; w < 8; w++) s += warp_sums[w];
        g_partials[(blockIdx.z * NBY + blockIdx.y) * NBX + blockIdx.x] = s;
    }
}

// stage 1: 32 blocks x 256 threads, each block sums 768 partials
__global__ void ssim_reduce1() {
    int t = threadIdx.x;
    int base = blockIdx.x * 768;
    double s = (double)g_partials[base + t]
             + (double)g_partials[base + t + 256]
             + (double)g_partials[base + t + 512];
    #pragma unroll
    for (int o = 16; o; o >>= 1) s += __shfl_xor_sync(0xffffffffu, s, o);
    __shared__ double ws[8];
    if ((t & 31) == 0) ws[t >> 5] = s;
    __syncthreads();
    if (t == 0) {
        double v = 0.0;
        #pragma unroll
        for (int w = 0; w < 8; w++) v += ws[w];
        g_p2[blockIdx.x] = v;
    }
}

// stage 2: single warp
__global__ void ssim_reduce2(float* __restrict__ out) {
    int t = threadIdx.x;
    double v = g_p2[t];
    #pragma unroll
    for (int o = 16; o; o >>= 1) v += __shfl_xor_sync(0xffffffffu, v, o);
    if (t == 0) out[0] = (float)(v / (3.0 * 25165824.0));  // 3 maps * 32*3*512*512
}

extern "C" void kernel_launch(void* const* d_in, const int* in_sizes, int n_in,
                              void* d_out, int out_size) {
    const float* img1 = (const float*)d_in[0];
    const float* img2 = (const float*)d_in[1];
    constexpr int SMEM_BYTES = 4 * PLANE * 8 + 2 * PLANE * 4; // 55040
    cudaFuncSetAttribute(ssim_main, cudaFuncAttributeMaxDynamicSharedMemorySize, SMEM_BYTES);
    dim3 grid(NBX, NBY, NBZ);
    // 3 nops put ssim_main at global launch index 5 == ncu's -s 5 -c 1 slot
    // (verified R3..R6: profile hit ssim_main).
    ssim_nop<<<1, 32>>>();
    ssim_nop<<<1, 32>>>();
    ssim_nop<<<1, 32>>>();
    ssim_main<<<grid, 256, SMEM_BYTES>>>(img1, img2);
    ssim_reduce1<<<32, 256>>>();
    ssim_reduce2<<<1, 32>>>((float*)d_out);
}

// round 8
// speedup vs baseline: 1.0357x; 1.0039x over previous
#include <cuda_runtime.h>

#define IMG_H 512
#define IMG_W 512
#define TH 32
#define TW 32
#define HALO 5
#define INW (TW + 2*HALO)   // 42 vertical-result columns
#define SW  (INW + 1)       // 43, odd stride vs 32 banks (conflict-free, proven R5)
#define PLANE (TH*SW)       // 1376
#define NBX (IMG_W/TW)      // 16
#define NBY (IMG_H/TH)      // 16
#define NBZ 96
#define NBLOCKS (NBX*NBY*NBZ)  // 24576
#define CHUNK 4
#define NCHUNKS (TH/CHUNK)     // 8
#define VITEMS (INW*NCHUNKS)   // 336 vertical work items

typedef unsigned long long ull;

__device__ float  g_partials[NBLOCKS];
__device__ double g_p2[32];

// ---- packed f32x2 helpers (sm_103a FFMA2 path) ----
__device__ __forceinline__ ull pk2(float lo, float hi) {
    ull r; asm("mov.b64 %0, {%1,%2};" : "=l"(r) : "f"(lo), "f"(hi)); return r;
}
__device__ __forceinline__ void upk2(ull v, float& lo, float& hi) {
    asm("mov.b64 {%0,%1}, %2;" : "=f"(lo), "=f"(hi) : "l"(v));
}
__device__ __forceinline__ ull fma2(ull a, ull b, ull c) {
    ull r; asm("fma.rn.f32x2 %0, %1, %2, %3;" : "=l"(r) : "l"(a), "l"(b), "l"(c)); return r;
}
__device__ __forceinline__ ull mul2(ull a, ull b) {
    ull r; asm("mul.rn.f32x2 %0, %1, %2;" : "=l"(r) : "l"(a), "l"(b)); return r;
}
__device__ __forceinline__ ull add2(ull a, ull b) {
    ull r; asm("add.rn.f32x2 %0, %1, %2;" : "=l"(r) : "l"(a), "l"(b)); return r;
}

// packed pair SSIM: 2 pixels at once; subs via exact fma(-1,b,a) so rounding
// matches the scalar version bit-for-bit (verified R3: same rel_err).
__device__ __forceinline__ float ssim_pair(ull m1p, ull m2p, ull e11p, ull e22p, ull e12p) {
    const ull C1p  = pk2(1e-4f, 1e-4f);
    const ull C2p  = pk2(9e-4f, 9e-4f);
    const ull two  = pk2(2.0f, 2.0f);
    const ull neg1 = pk2(-1.0f, -1.0f);
    ull mu11 = mul2(m1p, m1p);
    ull mu22 = mul2(m2p, m2p);
    ull mu12 = mul2(m1p, m2p);
    ull t1  = fma2(two, mu12, C1p);
    ull s12 = fma2(neg1, mu12, e12p);
    ull t2  = fma2(two, s12, C2p);
    ull num = mul2(t1, t2);
    ull d1  = add2(add2(mu11, mu22), C1p);
    ull sa  = fma2(neg1, mu11, e11p);
    ull sb  = fma2(neg1, mu22, e22p);
    ull d2  = add2(add2(sa, sb), C2p);
    ull den = mul2(d1, d2);
    float n0, n1, d0, dd;
    upk2(num, n0, n1); upk2(den, d0, dd);
    return __fdividef(n0, d0) + __fdividef(n1, dd);
}

__global__ void ssim_nop() {}

// Weight symmetry: W11[k]==W11[10-k], W5[m]==W5[4-m]; mixed pack inherits it.
#define W2IDX(k) ((k) < 6 ? (k) : 10 - (k))
#define U2IDX(m) ((m) < 3 ? (m) : 4 - (m))

__global__ void __launch_bounds__(256, 3)
ssim_main(const float* __restrict__ g1, const float* __restrict__ g2) {
    // Gaussian weights (sigma=1.5), computed offline in double then cast.
    constexpr float W11[11] = {
        0.00102838f, 0.00759876f, 0.03600077f, 0.10936069f, 0.21300552f,
        0.26601172f,
        0.21300552f, 0.10936069f, 0.03600077f, 0.00759876f, 0.00102838f };
    constexpr float W5[5] = {
        0.12007838f, 0.23388074f, 0.29208172f, 0.23388074f, 0.12007838f };

    extern __shared__ float vp[];      // 10 planes of TH x SW (v5: 0..4, v11: 5..9)

    const int t = threadIdx.x;
    const int r0 = blockIdx.y * TH;
    const int c0 = blockIdx.x * TW;
    const float* i1 = g1 + (size_t)blockIdx.z * (IMG_H * IMG_W);
    const float* i2 = g2 + (size_t)blockIdx.z * (IMG_H * IMG_W);

    ull W2d[6], U2d[3];
    #pragma unroll
    for (int i = 0; i < 6; i++) W2d[i] = pk2(W11[i], W11[i]);
    #pragma unroll
    for (int i = 0; i < 3; i++) U2d[i] = pk2(W5[i], W5[i]);

    // ---- vertical pass: global -> regs (14-row span) -> scatter -> vp ----
    {
        // mixed xy weight packs: (W11[k], W5[k-3] or 0); symmetric -> 6 distinct.
        // Live range confined to this scope (ends at __syncthreads).
        ull WXd[6];
        #pragma unroll
        for (int i = 0; i < 6; i++)
            WXd[i] = pk2(W11[i], (i >= 3) ? W5[i-3] : 0.0f);

        for (int i = t; i < VITEMS; i += 256) {
            int chunk = i / INW;          // 0..7
            int vcol  = i - chunk * INW;  // 0..41
            int gc = c0 - HALO + vcol;
            int grb = r0 + CHUNK * chunk - HALO;
            bool colok = (unsigned)gc < IMG_W;

            ull P11[CHUNK], S11[CHUNK], P5[CHUNK], S5[CHUNK], XP[CHUNK];
            #pragma unroll
            for (int o = 0; o < CHUNK; o++) {
                P11[o] = S11[o] = P5[o] = S5[o] = XP[o] = 0ULL;
            }
            #pragma unroll
            for (int j = 0; j < CHUNK + 10; j++) {   // 14 input rows
                int gr = grb + j;
                float x = 0.f, y = 0.f;
                if (colok && (unsigned)gr < IMG_H) {
                    int gi = gr * IMG_W + gc;
                    x = i1[gi];
                    y = i2[gi];
                }
                ull p  = pk2(x, y);
                ull sq = mul2(p, p);
                float xy = x * y;
                ull xyp = pk2(xy, xy);
                #pragma unroll
                for (int o = 0; o < CHUNK; o++) {
                    int k = j - o;                 // tap index for output row o
                    if (k >= 0 && k < 11) {
                        P11[o] = fma2(W2d[W2IDX(k)], p,   P11[o]);
                        S11[o] = fma2(W2d[W2IDX(k)], sq,  S11[o]);
                        XP [o] = fma2(WXd[W2IDX(k)], xyp, XP [o]);  // (xy11, xy5)
                    }
                    if (k >= 3 && k < 8) {
                        P5[o] = fma2(U2d[U2IDX(k-3)], p,  P5[o]);
                        S5[o] = fma2(U2d[U2IDX(k-3)], sq, S5[o]);
                    }
                }
            }
            #pragma unroll
            for (int o = 0; o < CHUNK; o++) {
                int off = (CHUNK * chunk + o) * SW + vcol;
                float lo, hi, x11, x5;
                upk2(P5[o], lo, hi);  vp[0*PLANE + off] = lo; vp[1*PLANE + off] = hi;
                upk2(S5[o], lo, hi);  vp[2*PLANE + off] = lo; vp[3*PLANE + off] = hi;
                upk2(XP[o], x11, x5);
                vp[4*PLANE + off] = x5;
                upk2(P11[o], lo, hi); vp[5*PLANE + off] = lo; vp[6*PLANE + off] = hi;
                upk2(S11[o], lo, hi); vp[7*PLANE + off] = lo; vp[8*PLANE + off] = hi;
                vp[9*PLANE + off] = x11;
            }
        }
    }
    __syncthreads();

    // ---- horizontal pass (4 consecutive output columns per thread) ----
    const int rr = t >> 3;          // 0..31
    const int cc = (t & 7) * 4;     // 0,4,...,28
    const float* b5  = vp + rr * SW + cc;
    const float* b11 = b5 + 5 * PLANE;

    float lsum = 0.f;

    // map (kh=5, kw=11): h11 over v5 planes
    {
        ull aP[4], aS[4];
        float aC[4];
        #pragma unroll
        for (int p = 0; p < 4; p++) { aP[p] = 0ULL; aS[p] = 0ULL; aC[p] = 0.f; }
        #pragma unroll
        for (int dx = 0; dx < 14; dx++) {
            float v0 = b5[dx];
            float v1 = b5[PLANE + dx];
            float v2 = b5[2*PLANE + dx];
            float v3 = b5[3*PLANE + dx];
            float v4 = b5[4*PLANE + dx];
            ull pP = pk2(v0, v1);
            ull pS = pk2(v2, v3);
            #pragma unroll
            for (int p = 0; p < 4; p++) {
                int k = dx - p;
                if (k >= 0 && k < 11) {
                    aP[p] = fma2(W2d[W2IDX(k)], pP, aP[p]);
                    aS[p] = fma2(W2d[W2IDX(k)], pS, aS[p]);
                    aC[p] = fmaf(W11[k], v4, aC[p]);
                }
            }
        }
        // packed epilogue: pixel pairs (0,1), (2,3)
        #pragma unroll
        for (int q = 0; q < 2; q++) {
            int p0 = 2*q, p1 = 2*q + 1;
            float x0, y0, x1, y1;
            upk2(aP[p0], x0, y0); upk2(aP[p1], x1, y1);
            ull m1p = pk2(x0, x1), m2p = pk2(y0, y1);
            upk2(aS[p0], x0, y0); upk2(aS[p1], x1, y1);
            lsum += ssim_pair(m1p, m2p, pk2(x0, x1), pk2(y0, y1), pk2(aC[p0], aC[p1]));
        }
    }

    // maps (11,5) via h5 and (11,11) via h11, both over v11 planes
    {
        ull bP[4], bS[4], cP[4], cS[4];
        float bC[4], cC[4];
        #pragma unroll
        for (int p = 0; p < 4; p++) {
            bP[p] = bS[p] = cP[p] = cS[p] = 0ULL;
            bC[p] = cC[p] = 0.f;
        }
        #pragma unroll
        for (int dx = 0; dx < 14; dx++) {
            float v0 = b11[dx];
            float v1 = b11[PLANE + dx];
            float v2 = b11[2*PLANE + dx];
            float v3 = b11[3*PLANE + dx];
            float v4 = b11[4*PLANE + dx];
            ull pP = pk2(v0, v1);
            ull pS = pk2(v2, v3);
            #pragma unroll
            for (int p = 0; p < 4; p++) {
                int k = dx - p;
                if (k >= 0 && k < 11) {
                    cP[p] = fma2(W2d[W2IDX(k)], pP, cP[p]);
                    cS[p] = fma2(W2d[W2IDX(k)], pS, cS[p]);
                    cC[p] = fmaf(W11[k], v4, cC[p]);
                }
                int m = k - 3;
                if (m >= 0 && m < 5) {
                    bP[p] = fma2(U2d[U2IDX(m)], pP, bP[p]);
                    bS[p] = fma2(U2d[U2IDX(m)], pS, bS[p]);
                    bC[p] = fmaf(W5[m], v4, bC[p]);
                }
            }
        }
        #pragma unroll
        for (int q = 0; q < 2; q++) {
            int p0 = 2*q, p1 = 2*q + 1;
            float x0, y0, x1, y1;
            // map B
            upk2(bP[p0], x0, y0); upk2(bP[p1], x1, y1);
            ull m1p = pk2(x0, x1), m2p = pk2(y0, y1);
            upk2(bS[p0], x0, y0); upk2(bS[p1], x1, y1);
            lsum += ssim_pair(m1p, m2p, pk2(x0, x1), pk2(y0, y1), pk2(bC[p0], bC[p1]));
            // map C
            upk2(cP[p0], x0, y0); upk2(cP[p1], x1, y1);
            m1p = pk2(x0, x1); m2p = pk2(y0, y1);
            upk2(cS[p0], x0, y0); upk2(cS[p1], x1, y1);
            lsum += ssim_pair(m1p, m2p, pk2(x0, x1), pk2(y0, y1), pk2(cC[p0], cC[p1]));
        }
    }

    // ---- block reduction -> per-block partial ----
    #pragma unroll
    for (int o = 16; o; o >>= 1) lsum += __shfl_xor_sync(0xffffffffu, lsum, o);
    __shared__ float warp_sums[8];
    if ((t & 31) == 0) warp_sums[t >> 5] = lsum;
    __syncthreads();
    if (t == 0) {
        float s = 0.f;
        #pragma unroll
        for (int w = 0; w < 8; w++) s += warp_sums[w];
        g_partials[(blockIdx.z * NBY + blockIdx.y) * NBX + blockIdx.x] = s;
    }
}

// stage 1: 32 blocks x 256 threads, each block sums 768 partials
__global__ void ssim_reduce1() {
    int t = threadIdx.x;
    int base = blockIdx.x * 768;
    double s = (double)g_partials[base + t]
             + (double)g_partials[base + t + 256]
             + (double)g_partials[base + t + 512];
    #pragma unroll
    for (int o = 16; o; o >>= 1) s += __shfl_xor_sync(0xffffffffu, s, o);
    __shared__ double ws[8];
    if ((t & 31) == 0) ws[t >> 5] = s;
    __syncthreads();
    if (t == 0) {
        double v = 0.0;
        #pragma unroll
        for (int w = 0; w < 8; w++) v += ws[w];
        g_p2[blockIdx.x] = v;
    }
}

// stage 2: single warp
__global__ void ssim_reduce2(float* __restrict__ out) {
    int t = threadIdx.x;
    double v = g_p2[t];
    #pragma unroll
    for (int o = 16; o; o >>= 1) v += __shfl_xor_sync(0xffffffffu, v, o);
    if (t == 0) out[0] = (float)(v / (3.0 * 25165824.0));  // 3 maps * 32*3*512*512
}

extern "C" void kernel_launch(void* const* d_in, const int* in_sizes, int n_in,
                              void* d_out, int out_size) {
    const float* img1 = (const float*)d_in[0];
    const float* img2 = (const float*)d_in[1];
    constexpr int SMEM_BYTES = 10 * PLANE * (int)sizeof(float); // 55040
    cudaFuncSetAttribute(ssim_main, cudaFuncAttributeMaxDynamicSharedMemorySize, SMEM_BYTES);
    dim3 grid(NBX, NBY, NBZ);
    // 3 nops put ssim_main at global launch index 5 == ncu's -s 5 -c 1 slot
    // (verified R3..R7: profile hit ssim_main).
    ssim_nop<<<1, 32>>>();
    ssim_nop<<<1, 32>>>();
    ssim_nop<<<1, 32>>>();
    ssim_main<<<grid, 256, SMEM_BYTES>>>(img1, img2);
    ssim_reduce1<<<32, 256>>>();
    ssim_reduce2<<<1, 32>>>((float*)d_out);
}

// round 9
// speedup vs baseline: 1.2771x; 1.2331x over previous
#include <cuda_runtime.h>

#define IMG_H 512
#define IMG_W 512
#define TH 32
#define TW 32
#define HALO 5
#define INW (TW + 2*HALO)   // 42 vertical-result columns
#define SW  (INW + 1)       // 43, odd stride vs 32 banks (conflict-free, proven R5)
#define PLANE (TH*SW)       // 1376
#define NBX (IMG_W/TW)      // 16
#define NBY (IMG_H/TH)      // 16
#define NBZ 96
#define NBLOCKS (NBX*NBY*NBZ)  // 24576
#define CHUNK 4
#define NCHUNKS (TH/CHUNK)     // 8
#define VITEMS (INW*NCHUNKS)   // 336 vertical work items

typedef unsigned long long ull;

__device__ float  g_partials[NBLOCKS];
__device__ double g_p2[32];

// ---- packed f32x2 helpers (sm_103a FFMA2 path) ----
__device__ __forceinline__ ull pk2(float lo, float hi) {
    ull r; asm("mov.b64 %0, {%1,%2};" : "=l"(r) : "f"(lo), "f"(hi)); return r;
}
__device__ __forceinline__ void upk2(ull v, float& lo, float& hi) {
    asm("mov.b64 {%0,%1}, %2;" : "=f"(lo), "=f"(hi) : "l"(v));
}
__device__ __forceinline__ ull fma2(ull a, ull b, ull c) {
    ull r; asm("fma.rn.f32x2 %0, %1, %2, %3;" : "=l"(r) : "l"(a), "l"(b), "l"(c)); return r;
}
__device__ __forceinline__ ull mul2(ull a, ull b) {
    ull r; asm("mul.rn.f32x2 %0, %1, %2;" : "=l"(r) : "l"(a), "l"(b)); return r;
}

// 4-field SSIM: m1=mu1, m2=mu2, S=E[x^2+y^2], Q=E[xy]
__device__ __forceinline__ float ssim_val4(float m1, float m2, float S, float Q) {
    const float C1 = 1e-4f;
    const float C2 = 9e-4f;
    float mu11 = m1 * m1;
    float mu22 = m2 * m2;
    float mu12 = m1 * m2;
    float num = (2.0f * mu12 + C1) * (2.0f * (Q - mu12) + C2);
    float den = (mu11 + mu22 + C1) * ((S - mu11 - mu22) + C2);
    return __fdividef(num, den);
}

__global__ void ssim_nop() {}

__global__ void __launch_bounds__(256, 3)
ssim_main(const float* __restrict__ g1, const float* __restrict__ g2) {
    // Gaussian weights (sigma=1.5), computed offline in double then cast.
    constexpr float W11[11] = {
        0.00102838f, 0.00759876f, 0.03600077f, 0.10936069f, 0.21300552f,
        0.26601172f,
        0.21300552f, 0.10936069f, 0.03600077f, 0.00759876f, 0.00102838f };
    constexpr float W5[5] = {
        0.12007838f, 0.23388074f, 0.29208172f, 0.23388074f, 0.12007838f };

    // 8 scalar planes: [0]=mu1_5 [1]=mu2_5 [2]=s5 [3]=q5
    //                  [4]=mu1_11 [5]=mu2_11 [6]=s11 [7]=q11
    extern __shared__ float vp[];

    const int t = threadIdx.x;
    const int r0 = blockIdx.y * TH;
    const int c0 = blockIdx.x * TW;
    const float* i1 = g1 + (size_t)blockIdx.z * (IMG_H * IMG_W);
    const float* i2 = g2 + (size_t)blockIdx.z * (IMG_H * IMG_W);

    ull W2[11], U2[5];
    #pragma unroll
    for (int i = 0; i < 11; i++) W2[i] = pk2(W11[i], W11[i]);
    #pragma unroll
    for (int i = 0; i < 5; i++)  U2[i] = pk2(W5[i], W5[i]);

    // ---- vertical pass: global -> regs (14-row span) -> scatter -> vp ----
    for (int i = t; i < VITEMS; i += 256) {
        int chunk = i / INW;          // 0..7
        int vcol  = i - chunk * INW;  // 0..41
        int gc = c0 - HALO + vcol;
        int grb = r0 + CHUNK * chunk - HALO;
        bool colok = (unsigned)gc < IMG_W;

        ull P11[CHUNK], SQ11[CHUNK], P5[CHUNK], SQ5[CHUNK];
        #pragma unroll
        for (int o = 0; o < CHUNK; o++) {
            P11[o] = SQ11[o] = P5[o] = SQ5[o] = 0ULL;
        }
        #pragma unroll
        for (int j = 0; j < CHUNK + 10; j++) {   // 14 input rows
            int gr = grb + j;
            float x = 0.f, y = 0.f;
            if (colok && (unsigned)gr < IMG_H) {
                int gi = gr * IMG_W + gc;
                x = i1[gi];
                y = i2[gi];
            }
            ull p = pk2(x, y);
            float xx, yy;
            upk2(mul2(p, p), xx, yy);
            ull sq = pk2(xx + yy, x * y);        // (s, q)
            #pragma unroll
            for (int o = 0; o < CHUNK; o++) {
                int k = j - o;                   // tap index for output row o
                if (k >= 0 && k < 11) {
                    P11[o]  = fma2(W2[k], p,  P11[o]);
                    SQ11[o] = fma2(W2[k], sq, SQ11[o]);
                }
                if (k >= 3 && k < 8) {
                    P5[o]  = fma2(U2[k-3], p,  P5[o]);
                    SQ5[o] = fma2(U2[k-3], sq, SQ5[o]);
                }
            }
        }
        #pragma unroll
        for (int o = 0; o < CHUNK; o++) {
            int off = (CHUNK * chunk + o) * SW + vcol;
            float lo, hi;
            upk2(P5[o], lo, hi);   vp[0*PLANE + off] = lo; vp[1*PLANE + off] = hi;
            upk2(SQ5[o], lo, hi);  vp[2*PLANE + off] = lo; vp[3*PLANE + off] = hi;
            upk2(P11[o], lo, hi);  vp[4*PLANE + off] = lo; vp[5*PLANE + off] = hi;
            upk2(SQ11[o], lo, hi); vp[6*PLANE + off] = lo; vp[7*PLANE + off] = hi;
        }
    }
    __syncthreads();

    // ---- horizontal pass (4 consecutive output columns per thread) ----
    const int rr = t >> 3;          // 0..31
    const int cc = (t & 7) * 4;     // 0,4,...,28
    const float* b5  = vp + rr * SW + cc;
    const float* b11 = b5 + 4 * PLANE;

    float lsum = 0.f;

    // map (kh=5, kw=11): h11 over v5 planes
    {
        ull aP[4], aSQ[4];
        #pragma unroll
        for (int p = 0; p < 4; p++) { aP[p] = 0ULL; aSQ[p] = 0ULL; }
        #pragma unroll
        for (int dx = 0; dx < 14; dx++) {
            float v0 = b5[dx];
            float v1 = b5[PLANE + dx];
            float v2 = b5[2*PLANE + dx];
            float v3 = b5[3*PLANE + dx];
            ull pP = pk2(v0, v1);
            ull pS = pk2(v2, v3);
            #pragma unroll
            for (int p = 0; p < 4; p++) {
                int k = dx - p;
                if (k >= 0 && k < 11) {
                    aP[p]  = fma2(W2[k], pP, aP[p]);
                    aSQ[p] = fma2(W2[k], pS, aSQ[p]);
                }
            }
        }
        #pragma unroll
        for (int p = 0; p < 4; p++) {
            float m1, m2, S, Q;
            upk2(aP[p], m1, m2); upk2(aSQ[p], S, Q);
            lsum += ssim_val4(m1, m2, S, Q);
        }
    }

    // maps (11,5) via h5 and (11,11) via h11, both over v11 planes
    {
        ull bP[4], bSQ[4], cP[4], cSQ[4];
        #pragma unroll
        for (int p = 0; p < 4; p++) {
            bP[p] = bSQ[p] = cP[p] = cSQ[p] = 0ULL;
        }
        #pragma unroll
        for (int dx = 0; dx < 14; dx++) {
            float v0 = b11[dx];
            float v1 = b11[PLANE + dx];
            float v2 = b11[2*PLANE + dx];
            float v3 = b11[3*PLANE + dx];
            ull pP = pk2(v0, v1);
            ull pS = pk2(v2, v3);
            #pragma unroll
            for (int p = 0; p < 4; p++) {
                int k = dx - p;
                if (k >= 0 && k < 11) {
                    cP[p]  = fma2(W2[k], pP, cP[p]);
                    cSQ[p] = fma2(W2[k], pS, cSQ[p]);
                }
                int m = k - 3;
                if (m >= 0 && m < 5) {
                    bP[p]  = fma2(U2[m], pP, bP[p]);
                    bSQ[p] = fma2(U2[m], pS, bSQ[p]);
                }
            }
        }
        #pragma unroll
        for (int p = 0; p < 4; p++) {
            float m1, m2, S, Q;
            upk2(bP[p], m1, m2); upk2(bSQ[p], S, Q);
            lsum += ssim_val4(m1, m2, S, Q);
            upk2(cP[p], m1, m2); upk2(cSQ[p], S, Q);
            lsum += ssim_val4(m1, m2, S, Q);
        }
    }

    // ---- block reduction -> per-block partial ----
    #pragma unroll
    for (int o = 16; o; o >>= 1) lsum += __shfl_xor_sync(0xffffffffu, lsum, o);
    __shared__ float warp_sums[8];
    if ((t & 31) == 0) warp_sums[t >> 5] = lsum;
    __syncthreads();
    if (t == 0) {
        float s = 0.f;
        #pragma unroll
        for (int w = 0; w < 8; w++) s += warp_sums[w];
        g_partials[(blockIdx.z * NBY + blockIdx.y) * NBX + blockIdx.x] = s;
    }
}

// stage 1: 32 blocks x 256 threads, each block sums 768 partials
__global__ void ssim_reduce1() {
    int t = threadIdx.x;
    int base = blockIdx.x * 768;
    double s = (double)g_partials[base + t]
             + (double)g_partials[base + t + 256]
             + (double)g_partials[base + t + 512];
    #pragma unroll
    for (int o = 16; o; o >>= 1) s += __shfl_xor_sync(0xffffffffu, s, o);
    __shared__ double ws[8];
    if ((t & 31) == 0) ws[t >> 5] = s;
    __syncthreads();
    if (t == 0) {
        double v = 0.0;
        #pragma unroll
        for (int w = 0; w < 8; w++) v += ws[w];
        g_p2[blockIdx.x] = v;
    }
}

// stage 2: single warp
__global__ void ssim_reduce2(float* __restrict__ out) {
    int t = threadIdx.x;
    double v = g_p2[t];
    #pragma unroll
    for (int o = 16; o; o >>= 1) v += __shfl_xor_sync(0xffffffffu, v, o);
    if (t == 0) out[0] = (float)(v / (3.0 * 25165824.0));  // 3 maps * 32*3*512*512
}

extern "C" void kernel_launch(void* const* d_in, const int* in_sizes, int n_in,
                              void* d_out, int out_size) {
    const float* img1 = (const float*)d_in[0];
    const float* img2 = (const float*)d_in[1];
    constexpr int SMEM_BYTES = 8 * PLANE * (int)sizeof(float); // 44032
    cudaFuncSetAttribute(ssim_main, cudaFuncAttributeMaxDynamicSharedMemorySize, SMEM_BYTES);
    dim3 grid(NBX, NBY, NBZ);
    // 3 nops put ssim_main at global launch index 5 == ncu's -s 5 -c 1 slot
    // (verified R3..R8: profile hit ssim_main).
    ssim_nop<<<1, 32>>>();
    ssim_nop<<<1, 32>>>();
    ssim_nop<<<1, 32>>>();
    ssim_main<<<grid, 256, SMEM_BYTES>>>(img1, img2);
    ssim_reduce1<<<32, 256>>>();
    ssim_reduce2<<<1, 32>>>((float*)d_out);
}